// round 9
// baseline (speedup 1.0000x reference)
#include <cuda_runtime.h>
#include <cstdint>

#define DT_C 0.02f
#define GRAV_C 10.0f
#define THRUST_C 6.0f
#define TORQUE_C 1.0f
#define TPB 128

// Per-tile staging layout (floats): P | x | z | u  (all gmem-contiguous per tile)
#define FOFF_P 0
#define FOFF_X 4608
#define FOFF_Z 5376
#define FOFF_U 5760
#define BUF_FLOATS 6016
#define TILE_BYTES 24064           // 6016 * 4
#define P_BYTES 18432
#define X_BYTES 3072
#define Z_BYTES 1536
#define U_BYTES 1024

__device__ __forceinline__ void mbar_init(uint32_t mbar, uint32_t cnt) {
    asm volatile("mbarrier.init.shared.b64 [%0], %1;" :: "r"(mbar), "r"(cnt) : "memory");
}
__device__ __forceinline__ void mbar_expect_tx(uint32_t mbar, uint32_t bytes) {
    asm volatile("mbarrier.arrive.expect_tx.shared.b64 _, [%0], %1;"
                 :: "r"(mbar), "r"(bytes) : "memory");
}
__device__ __forceinline__ void mbar_wait(uint32_t mbar, uint32_t parity) {
    asm volatile(
        "{\n\t.reg .pred P1;\n\t"
        "WAIT_%=:\n\t"
        "mbarrier.try_wait.parity.acquire.cta.shared::cta.b64 P1, [%0], %1, 0x989680;\n\t"
        "@P1 bra.uni DONE_%=;\n\t"
        "bra.uni WAIT_%=;\n\t"
        "DONE_%=:\n\t}"
        :: "r"(mbar), "r"(parity) : "memory");
}
__device__ __forceinline__ void tma_load_1d(uint32_t smem, const void* gmem,
                                            uint32_t bytes, uint32_t mbar) {
    asm volatile("cp.async.bulk.shared::cta.global.mbarrier::complete_tx::bytes "
                 "[%0], [%1], %2, [%3];"
                 :: "r"(smem), "l"(gmem), "r"(bytes), "r"(mbar) : "memory");
}
__device__ __forceinline__ void tma_store_1d(void* gmem, uint32_t smem, uint32_t bytes) {
    asm volatile("cp.async.bulk.global.shared::cta.bulk_group [%0], [%1], %2;"
                 :: "l"(gmem), "r"(smem), "r"(bytes) : "memory");
}
__device__ __forceinline__ void tma_store_commit() {
    asm volatile("cp.async.bulk.commit_group;" ::: "memory");
}
__device__ __forceinline__ void tma_store_wait_read0() {
    asm volatile("cp.async.bulk.wait_group.read 0;" ::: "memory");
}
__device__ __forceinline__ void fence_async_shared() {
    asm volatile("fence.proxy.async.shared::cta;" ::: "memory");
}

__global__ __launch_bounds__(TPB, 4)
void ekf_kernel(const float* __restrict__ z, const float* __restrict__ u,
                const float* __restrict__ xprev, const float* __restrict__ Pprev,
                const float* __restrict__ qld, const float* __restrict__ qod,
                const float* __restrict__ rld, const float* __restrict__ rod,
                float* __restrict__ out_x, float* __restrict__ out_P, int B) {
    __shared__ alignas(128) float sBuf[2][BUF_FLOATS];   // 48128 B
    __shared__ alignas(8) uint64_t sMbar[2];
    __shared__ float sQ[36];
    __shared__ float sR[9];

    const int t = threadIdx.x;
    const int G = gridDim.x;
    const int bid = blockIdx.x;
    const int ntot = (B + TPB - 1) / TPB;
    const int nt = (ntot > bid) ? ((ntot - bid + G - 1) / G) : 0;
    const uint32_t mb0 = (uint32_t)__cvta_generic_to_shared(&sMbar[0]);
    const uint32_t mb1 = (uint32_t)__cvta_generic_to_shared(&sMbar[1]);
    const uint32_t sb0 = (uint32_t)__cvta_generic_to_shared(&sBuf[0][0]);
    const uint32_t sb1 = (uint32_t)__cvta_generic_to_shared(&sBuf[1][0]);

    // ---- Build Q = L L^T + 1e-6 I (threads 0..35) and R (36..44) ----
    if (t < 36) {
        int i = t / 6, j = t % 6;
        float acc = (i == j) ? 1e-6f : 0.0f;
        #pragma unroll
        for (int k = 0; k < 6; k++) {
            float Lik = (k < i) ? qod[i * (i - 1) / 2 + k] : ((k == i) ? expf(qld[i]) : 0.0f);
            float Ljk = (k < j) ? qod[j * (j - 1) / 2 + k] : ((k == j) ? expf(qld[j]) : 0.0f);
            acc += Lik * Ljk;
        }
        sQ[t] = acc;
    } else if (t < 45) {
        int t2 = t - 36;
        int i = t2 / 3, j = t2 % 3;
        float acc = (i == j) ? 1e-6f : 0.0f;
        #pragma unroll
        for (int k = 0; k < 3; k++) {
            float Lik = (k < i) ? rod[i * (i - 1) / 2 + k] : ((k == i) ? expf(rld[i]) : 0.0f);
            float Ljk = (k < j) ? rod[j * (j - 1) / 2 + k] : ((k == j) ? expf(rld[j]) : 0.0f);
            acc += Lik * Ljk;
        }
        sR[t2] = acc;
    }
    if (t == 0) { mbar_init(mb0, 1); mbar_init(mb1, 1); }
    __syncthreads();                 // Q/R + mbarrier init visible (incl. to async proxy use below)

    if (nt == 0) return;

    // thread 0 issues all TMA ops
    auto issue_load = [&](int k) {
        int tile = bid + k * G;
        size_t base = (size_t)tile * TPB;
        if (base + TPB <= (size_t)B) {
            int p = k & 1;
            uint32_t sb = p ? sb1 : sb0;
            uint32_t mb = p ? mb1 : mb0;
            mbar_expect_tx(mb, TILE_BYTES);
            tma_load_1d(sb + FOFF_P * 4, Pprev + base * 36, P_BYTES, mb);
            tma_load_1d(sb + FOFF_X * 4, xprev + base * 6,  X_BYTES, mb);
            tma_load_1d(sb + FOFF_Z * 4, z + base * 3,      Z_BYTES, mb);
            tma_load_1d(sb + FOFF_U * 4, u + base * 2,      U_BYTES, mb);
        }
    };

    if (t == 0) {
        issue_load(0);
        if (nt > 1) issue_load(1);
    }

    for (int k = 0; k < nt; k++) {
        int p = k & 1;
        int tile = bid + k * G;
        size_t base = (size_t)tile * TPB;
        bool full = (base + TPB <= (size_t)B);
        int b = (int)base + t;
        bool active = (b < B);
        float* buf = &sBuf[p][0];

        if (full) mbar_wait(p ? mb1 : mb0, (uint32_t)((k >> 1) & 1));

        // ---- Gather inputs ----
        float Pf[36];
        float px = 0, py = 0, vx = 0, vy = 0, th = 0, om = 0;
        float u0 = 0, u1 = 0, z0 = 0, z1 = 0, z2 = 0;
        if (full) {
            const float4* p4 = reinterpret_cast<const float4*>(buf + FOFF_P);
            #pragma unroll
            for (int i = 0; i < 9; i++) {
                float4 v = p4[t * 9 + i];
                Pf[4 * i + 0] = v.x; Pf[4 * i + 1] = v.y;
                Pf[4 * i + 2] = v.z; Pf[4 * i + 3] = v.w;
            }
            const float2* x2 = reinterpret_cast<const float2*>(buf + FOFF_X);
            float2 a = x2[3 * t], bb = x2[3 * t + 1], cc = x2[3 * t + 2];
            px = a.x; py = a.y; vx = bb.x; vy = bb.y; th = cc.x; om = cc.y;
            z0 = buf[FOFF_Z + 3 * t]; z1 = buf[FOFF_Z + 3 * t + 1]; z2 = buf[FOFF_Z + 3 * t + 2];
            const float2* u2 = reinterpret_cast<const float2*>(buf + FOFF_U);
            float2 uu = u2[t];
            u0 = uu.x; u1 = uu.y;
        } else if (active) {
            const float4* p4 = reinterpret_cast<const float4*>(Pprev + (size_t)b * 36);
            #pragma unroll
            for (int i = 0; i < 9; i++) {
                float4 v = p4[i];
                Pf[4 * i + 0] = v.x; Pf[4 * i + 1] = v.y;
                Pf[4 * i + 2] = v.z; Pf[4 * i + 3] = v.w;
            }
            const float2* x2 = reinterpret_cast<const float2*>(xprev + (size_t)b * 6);
            float2 a = x2[0], bb = x2[1], cc = x2[2];
            px = a.x; py = a.y; vx = bb.x; vy = bb.y; th = cc.x; om = cc.y;
            float2 uu = reinterpret_cast<const float2*>(u)[b];
            u0 = uu.x; u1 = uu.y;
            z0 = z[(size_t)b * 3 + 0];
            z1 = z[(size_t)b * 3 + 1];
            z2 = z[(size_t)b * 3 + 2];
        } else {
            #pragma unroll
            for (int i = 0; i < 36; i++) Pf[i] = 0.0f;
        }
#define Pm(i, j) Pf[(i) * 6 + (j)]

        // ---- Dynamics + Jacobian coefficients ----
        float mp = fminf(fmaxf(u0, 0.0f), 1.0f);
        float s, c;
        __sincosf(th, &s, &c);
        float Tm = THRUST_C * mp;
        float nvx = vx + (-Tm * s) * DT_C;
        float nvy = vy + (Tm * c - GRAV_C) * DT_C;
        float nom = om + (TORQUE_C * u1) * DT_C;
        float npx = px + nvx * DT_C;
        float npy = py + nvy * DT_C;
        float nth = th + nom * DT_C;

        float a2 = -Tm * c * DT_C;   // F[2][4]
        float a3 = -Tm * s * DT_C;   // F[3][4]
        float a0 = a2 * DT_C;        // F[0][4]
        float a1 = a3 * DT_C;        // F[1][4]

        // ---- P_pred = F P F^T + Q (sparse F: row ops then col ops, in place) ----
        #pragma unroll
        for (int j = 0; j < 6; j++) {
            Pm(0, j) += DT_C * Pm(2, j) + a0 * Pm(4, j);
            Pm(1, j) += DT_C * Pm(3, j) + a1 * Pm(4, j);
            Pm(2, j) += a2 * Pm(4, j);
            Pm(3, j) += a3 * Pm(4, j);
            Pm(4, j) += DT_C * Pm(5, j);
        }
        #pragma unroll
        for (int i = 0; i < 6; i++) {
            Pm(i, 0) += DT_C * Pm(i, 2) + a0 * Pm(i, 4);
            Pm(i, 1) += DT_C * Pm(i, 3) + a1 * Pm(i, 4);
            Pm(i, 2) += a2 * Pm(i, 4);
            Pm(i, 3) += a3 * Pm(i, 4);
            Pm(i, 4) += DT_C * Pm(i, 5);
        }

        // ---- Upper triangle of P_pred + Q ----
        float up[21];
        {
            int kk = 0;
            #pragma unroll
            for (int i = 0; i < 6; i++)
                #pragma unroll
                for (int j = i; j < 6; j++) {
                    up[kk] = Pm(i, j) + sQ[i * 6 + j];
                    kk++;
                }
        }
#undef Pm
#define UIDX(i, j) ((i) * 6 - (i) * ((i) + 1) / 2 + (j))
#define US(i, j) ((i) <= (j) ? up[UIDX(i, j)] : up[UIDX(j, i)])

        // ---- S = P_pred[(0,1,4),(0,1,4)] + R ; symmetric 3x3 inverse ----
        float S00 = US(0, 0) + sR[0];
        float S01 = US(0, 1) + sR[1];
        float S02 = US(0, 4) + sR[2];
        float S11 = US(1, 1) + sR[4];
        float S12 = US(1, 4) + sR[5];
        float S22 = US(4, 4) + sR[8];

        float i00 = S11 * S22 - S12 * S12;
        float i01 = S02 * S12 - S01 * S22;
        float i02 = S01 * S12 - S02 * S11;
        float i11 = S00 * S22 - S02 * S02;
        float i12 = S01 * S02 - S00 * S12;
        float i22 = S00 * S11 - S01 * S01;
        float invdet = 1.0f / (S00 * i00 + S01 * i01 + S02 * i02);
        i00 *= invdet; i01 *= invdet; i02 *= invdet;
        i11 *= invdet; i12 *= invdet; i22 *= invdet;

        // ---- K[k] = Si * (P[0][k], P[1][k], P[4][k]) ----
        float K[6][3];
        #pragma unroll
        for (int kk = 0; kk < 6; kk++) {
            float h0 = US(0, kk), h1 = US(1, kk), h2 = US(4, kk);
            K[kk][0] = h0 * i00 + h1 * i01 + h2 * i02;
            K[kk][1] = h0 * i01 + h1 * i11 + h2 * i12;
            K[kk][2] = h0 * i02 + h1 * i12 + h2 * i22;
        }

        // ---- x_upd ----
        float y0 = z0 - npx, y1 = z1 - npy, y2 = z2 - nth;
        float xpred[6] = {npx, npy, nvx, nvy, nth, nom};
        float xout[6];
        #pragma unroll
        for (int i = 0; i < 6; i++)
            xout[i] = xpred[i] + K[i][0] * y0 + K[i][1] * y1 + K[i][2] * y2;

        // ---- P_upd = P_pred - K (H P_pred), symmetric ----
        float Pu[36];
        #pragma unroll
        for (int i = 0; i < 6; i++)
            #pragma unroll
            for (int j = i; j < 6; j++) {
                float v = US(i, j)
                    - K[i][0] * US(0, j) - K[i][1] * US(1, j) - K[i][2] * US(4, j);
                Pu[i * 6 + j] = v;
                Pu[j * 6 + i] = v;
            }
#undef US
#undef UIDX

        // ---- Stores ----
        if (full) {
            // Stage outputs into this tile's buffer (each thread overwrites only
            // its own already-consumed region), then TMA bulk store.
            float4* p4o = reinterpret_cast<float4*>(buf + FOFF_P);
            #pragma unroll
            for (int i = 0; i < 9; i++)
                p4o[t * 9 + i] = make_float4(Pu[4 * i], Pu[4 * i + 1], Pu[4 * i + 2], Pu[4 * i + 3]);
            #pragma unroll
            for (int i = 0; i < 6; i++) buf[FOFF_X + t * 6 + i] = xout[i];
            fence_async_shared();
            __syncthreads();          // all STS visible to async proxy
            if (t == 0) {
                tma_store_1d(out_P + base * 36, (p ? sb1 : sb0) + FOFF_P * 4, P_BYTES);
                tma_store_1d(out_x + base * 6,  (p ? sb1 : sb0) + FOFF_X * 4, X_BYTES);
                tma_store_commit();
                // Buffer p is re-loaded for tile k+2: its store's smem reads must
                // be done first. wait_group.read 0 covers it (and the older group).
                if (k + 2 < nt) {
                    tma_store_wait_read0();
                    issue_load(k + 2);
                }
            }
        } else {
            if (active) {
                float4* op4 = reinterpret_cast<float4*>(out_P + (size_t)b * 36);
                #pragma unroll
                for (int i = 0; i < 9; i++)
                    op4[i] = make_float4(Pu[4 * i], Pu[4 * i + 1], Pu[4 * i + 2], Pu[4 * i + 3]);
                float2* ox2 = reinterpret_cast<float2*>(out_x + (size_t)b * 6);
                ox2[0] = make_float2(xout[0], xout[1]);
                ox2[1] = make_float2(xout[2], xout[3]);
                ox2[2] = make_float2(xout[4], xout[5]);
            }
            // tiles after a partial tile are never full; no TMA bookkeeping needed
        }
    }
}

extern "C" void kernel_launch(void* const* d_in, const int* in_sizes, int n_in,
                              void* d_out, int out_size) {
    const float* z   = (const float*)d_in[0];
    const float* u   = (const float*)d_in[1];
    const float* xp  = (const float*)d_in[2];
    const float* Pp  = (const float*)d_in[3];
    const float* qld = (const float*)d_in[4];
    const float* qod = (const float*)d_in[5];
    const float* rld = (const float*)d_in[6];
    const float* rod = (const float*)d_in[7];

    int B = in_sizes[0] / 3;
    float* out_x = (float*)d_out;
    float* out_P = out_x + (size_t)B * 6;

    int ntot = (B + TPB - 1) / TPB;
    int grid = 608;                 // 4 CTAs/SM x 152 SMs
    if (grid > ntot) grid = ntot;

    ekf_kernel<<<grid, TPB>>>(z, u, xp, Pp, qld, qod, rld, rod, out_x, out_P, B);
}

// round 10
// speedup vs baseline: 1.0117x; 1.0117x over previous
#include <cuda_runtime.h>
#include <cstdint>

#define DT_C 0.02f
#define GRAV_C 10.0f
#define THRUST_C 6.0f
#define TORQUE_C 1.0f
#define TPB 128
#define P_BYTES 18432   // 128 * 36 * 4

__device__ __forceinline__ void mbar_init(uint32_t mbar, uint32_t cnt) {
    asm volatile("mbarrier.init.shared.b64 [%0], %1;" :: "r"(mbar), "r"(cnt) : "memory");
}
__device__ __forceinline__ void mbar_expect_tx(uint32_t mbar, uint32_t bytes) {
    asm volatile("mbarrier.arrive.expect_tx.shared.b64 _, [%0], %1;"
                 :: "r"(mbar), "r"(bytes) : "memory");
}
__device__ __forceinline__ void mbar_wait(uint32_t mbar, uint32_t parity) {
    asm volatile(
        "{\n\t.reg .pred P1;\n\t"
        "WAIT_%=:\n\t"
        "mbarrier.try_wait.parity.acquire.cta.shared::cta.b64 P1, [%0], %1, 0x989680;\n\t"
        "@P1 bra.uni DONE_%=;\n\t"
        "bra.uni WAIT_%=;\n\t"
        "DONE_%=:\n\t}"
        :: "r"(mbar), "r"(parity) : "memory");
}
__device__ __forceinline__ void tma_load_1d(uint32_t smem, const void* gmem,
                                            uint32_t bytes, uint32_t mbar) {
    asm volatile("cp.async.bulk.shared::cta.global.mbarrier::complete_tx::bytes "
                 "[%0], [%1], %2, [%3];"
                 :: "r"(smem), "l"(gmem), "r"(bytes), "r"(mbar) : "memory");
}
__device__ __forceinline__ void tma_store_1d(void* gmem, uint32_t smem, uint32_t bytes) {
    asm volatile("cp.async.bulk.global.shared::cta.bulk_group [%0], [%1], %2;"
                 :: "l"(gmem), "r"(smem), "r"(bytes) : "memory");
}
__device__ __forceinline__ void tma_store_commit() {
    asm volatile("cp.async.bulk.commit_group;" ::: "memory");
}
__device__ __forceinline__ void tma_store_wait_read0() {
    asm volatile("cp.async.bulk.wait_group.read 0;" ::: "memory");
}
__device__ __forceinline__ void fence_async_shared() {
    asm volatile("fence.proxy.async.shared::cta;" ::: "memory");
}

__global__ __launch_bounds__(TPB, 6)
void ekf_kernel(const float* __restrict__ z, const float* __restrict__ u,
                const float* __restrict__ xprev, const float* __restrict__ Pprev,
                const float* __restrict__ qld, const float* __restrict__ qod,
                const float* __restrict__ rld, const float* __restrict__ rod,
                float* __restrict__ out_x, float* __restrict__ out_P, int B) {
    __shared__ alignas(128) float4 sP[2][TPB * 9];   // 36864 B (static, <48K: no opt-in needed)
    __shared__ alignas(8) uint64_t sMbar[2];
    __shared__ float sQ[36];
    __shared__ float sR[9];

    const int t = threadIdx.x;
    const int G = gridDim.x;
    const int bid = blockIdx.x;
    const int ntot = (B + TPB - 1) / TPB;
    const int nt = (ntot > bid) ? ((ntot - bid + G - 1) / G) : 0;
    const uint32_t mb0 = (uint32_t)__cvta_generic_to_shared(&sMbar[0]);
    const uint32_t mb1 = (uint32_t)__cvta_generic_to_shared(&sMbar[1]);
    const uint32_t sb0 = (uint32_t)__cvta_generic_to_shared(&sP[0][0]);
    const uint32_t sb1 = (uint32_t)__cvta_generic_to_shared(&sP[1][0]);

    // ---- Build Q = L L^T + 1e-6 I (threads 0..35) and R (36..44) ----
    if (t < 36) {
        int i = t / 6, j = t % 6;
        float acc = (i == j) ? 1e-6f : 0.0f;
        #pragma unroll
        for (int k = 0; k < 6; k++) {
            float Lik = (k < i) ? qod[i * (i - 1) / 2 + k] : ((k == i) ? expf(qld[i]) : 0.0f);
            float Ljk = (k < j) ? qod[j * (j - 1) / 2 + k] : ((k == j) ? expf(qld[j]) : 0.0f);
            acc += Lik * Ljk;
        }
        sQ[t] = acc;
    } else if (t < 45) {
        int t2 = t - 36;
        int i = t2 / 3, j = t2 % 3;
        float acc = (i == j) ? 1e-6f : 0.0f;
        #pragma unroll
        for (int k = 0; k < 3; k++) {
            float Lik = (k < i) ? rod[i * (i - 1) / 2 + k] : ((k == i) ? expf(rld[i]) : 0.0f);
            float Ljk = (k < j) ? rod[j * (j - 1) / 2 + k] : ((k == j) ? expf(rld[j]) : 0.0f);
            acc += Lik * Ljk;
        }
        sR[t2] = acc;
    }
    if (t == 0) { mbar_init(mb0, 1); mbar_init(mb1, 1); }
    __syncthreads();   // Q/R + mbarrier init visible before any TMA use

    if (nt == 0) return;

    auto issue_load = [&](int k) {   // thread 0 only
        int tile = bid + k * G;
        size_t base = (size_t)tile * TPB;
        if (base + TPB <= (size_t)B) {
            int p = k & 1;
            mbar_expect_tx(p ? mb1 : mb0, P_BYTES);
            tma_load_1d((p ? sb1 : sb0), Pprev + base * 36, P_BYTES, p ? mb1 : mb0);
        }
    };

    if (t == 0) {
        issue_load(0);
        if (nt > 1) issue_load(1);
    }

    for (int k = 0; k < nt; k++) {
        int p = k & 1;
        int tile = bid + k * G;
        size_t base = (size_t)tile * TPB;
        bool full = (base + TPB <= (size_t)B);
        int b = (int)base + t;
        bool active = (b < B);

        // ---- Direct small loads (issued before the pipeline wait; overlap) ----
        float px = 0, py = 0, vx = 0, vy = 0, th = 0, om = 0;
        float u0 = 0, u1 = 0, z0 = 0, z1 = 0, z2 = 0;
        if (active) {
            const float2* x2 = reinterpret_cast<const float2*>(xprev + (size_t)b * 6);
            float2 a = x2[0], bb = x2[1], cc = x2[2];
            px = a.x; py = a.y; vx = bb.x; vy = bb.y; th = cc.x; om = cc.y;
            float2 uu = reinterpret_cast<const float2*>(u)[b];
            u0 = uu.x; u1 = uu.y;
            z0 = z[(size_t)b * 3 + 0];
            z1 = z[(size_t)b * 3 + 1];
            z2 = z[(size_t)b * 3 + 2];
        }

        // ---- Dynamics + Jacobian coefficients (independent of P) ----
        float mp = fminf(fmaxf(u0, 0.0f), 1.0f);
        float s, c;
        __sincosf(th, &s, &c);
        float Tm = THRUST_C * mp;
        float nvx = vx + (-Tm * s) * DT_C;
        float nvy = vy + (Tm * c - GRAV_C) * DT_C;
        float nom = om + (TORQUE_C * u1) * DT_C;
        float npx = px + nvx * DT_C;
        float npy = py + nvy * DT_C;
        float nth = th + nom * DT_C;

        float a2 = -Tm * c * DT_C;   // F[2][4]
        float a3 = -Tm * s * DT_C;   // F[3][4]
        float a0 = a2 * DT_C;        // F[0][4]
        float a1 = a3 * DT_C;        // F[1][4]

        if (full) mbar_wait(p ? mb1 : mb0, (uint32_t)((k >> 1) & 1));

        // ---- Fetch my P_prev ----
        float Pf[36];
        if (full) {
            const float4* p4 = &sP[p][0];
            #pragma unroll
            for (int i = 0; i < 9; i++) {
                float4 v = p4[t * 9 + i];
                Pf[4 * i + 0] = v.x; Pf[4 * i + 1] = v.y;
                Pf[4 * i + 2] = v.z; Pf[4 * i + 3] = v.w;
            }
        } else if (active) {
            const float4* p4 = reinterpret_cast<const float4*>(Pprev + (size_t)b * 36);
            #pragma unroll
            for (int i = 0; i < 9; i++) {
                float4 v = p4[i];
                Pf[4 * i + 0] = v.x; Pf[4 * i + 1] = v.y;
                Pf[4 * i + 2] = v.z; Pf[4 * i + 3] = v.w;
            }
        } else {
            #pragma unroll
            for (int i = 0; i < 36; i++) Pf[i] = 0.0f;
        }
#define Pm(i, j) Pf[(i) * 6 + (j)]

        // ---- P_pred = F P F^T + Q (sparse F: row ops then col ops, in place) ----
        #pragma unroll
        for (int j = 0; j < 6; j++) {
            Pm(0, j) += DT_C * Pm(2, j) + a0 * Pm(4, j);
            Pm(1, j) += DT_C * Pm(3, j) + a1 * Pm(4, j);
            Pm(2, j) += a2 * Pm(4, j);
            Pm(3, j) += a3 * Pm(4, j);
            Pm(4, j) += DT_C * Pm(5, j);
        }
        #pragma unroll
        for (int i = 0; i < 6; i++) {
            Pm(i, 0) += DT_C * Pm(i, 2) + a0 * Pm(i, 4);
            Pm(i, 1) += DT_C * Pm(i, 3) + a1 * Pm(i, 4);
            Pm(i, 2) += a2 * Pm(i, 4);
            Pm(i, 3) += a3 * Pm(i, 4);
            Pm(i, 4) += DT_C * Pm(i, 5);
        }

        // ---- Upper triangle of P_pred + Q ----
        float up[21];
        {
            int kk = 0;
            #pragma unroll
            for (int i = 0; i < 6; i++)
                #pragma unroll
                for (int j = i; j < 6; j++) {
                    up[kk] = Pm(i, j) + sQ[i * 6 + j];
                    kk++;
                }
        }
#undef Pm
#define UIDX(i, j) ((i) * 6 - (i) * ((i) + 1) / 2 + (j))
#define US(i, j) ((i) <= (j) ? up[UIDX(i, j)] : up[UIDX(j, i)])

        // ---- S = P_pred[(0,1,4),(0,1,4)] + R ; symmetric 3x3 inverse ----
        float S00 = US(0, 0) + sR[0];
        float S01 = US(0, 1) + sR[1];
        float S02 = US(0, 4) + sR[2];
        float S11 = US(1, 1) + sR[4];
        float S12 = US(1, 4) + sR[5];
        float S22 = US(4, 4) + sR[8];

        float i00 = S11 * S22 - S12 * S12;
        float i01 = S02 * S12 - S01 * S22;
        float i02 = S01 * S12 - S02 * S11;
        float i11 = S00 * S22 - S02 * S02;
        float i12 = S01 * S02 - S00 * S12;
        float i22 = S00 * S11 - S01 * S01;
        float invdet = 1.0f / (S00 * i00 + S01 * i01 + S02 * i02);
        i00 *= invdet; i01 *= invdet; i02 *= invdet;
        i11 *= invdet; i12 *= invdet; i22 *= invdet;

        // ---- K[k] = Si * (P[0][k], P[1][k], P[4][k]) ----
        float K[6][3];
        #pragma unroll
        for (int kk = 0; kk < 6; kk++) {
            float h0 = US(0, kk), h1 = US(1, kk), h2 = US(4, kk);
            K[kk][0] = h0 * i00 + h1 * i01 + h2 * i02;
            K[kk][1] = h0 * i01 + h1 * i11 + h2 * i12;
            K[kk][2] = h0 * i02 + h1 * i12 + h2 * i22;
        }

        // ---- x_upd (direct store, float2) ----
        float y0 = z0 - npx, y1 = z1 - npy, y2 = z2 - nth;
        if (active) {
            float xpred[6] = {npx, npy, nvx, nvy, nth, nom};
            float2* ox2 = reinterpret_cast<float2*>(out_x + (size_t)b * 6);
            #pragma unroll
            for (int i = 0; i < 3; i++) {
                float v0 = xpred[2 * i]     + K[2 * i][0] * y0 + K[2 * i][1] * y1 + K[2 * i][2] * y2;
                float v1 = xpred[2 * i + 1] + K[2 * i + 1][0] * y0 + K[2 * i + 1][1] * y1 + K[2 * i + 1][2] * y2;
                ox2[i] = make_float2(v0, v1);
            }
        }

        // ---- P_upd = P_pred - K (H P_pred), symmetric ----
        float Pu[36];
        #pragma unroll
        for (int i = 0; i < 6; i++)
            #pragma unroll
            for (int j = i; j < 6; j++) {
                float v = US(i, j)
                    - K[i][0] * US(0, j) - K[i][1] * US(1, j) - K[i][2] * US(4, j);
                Pu[i * 6 + j] = v;
                Pu[j * 6 + i] = v;
            }
#undef US
#undef UIDX

        // ---- P store ----
        if (full) {
            // Stage into the just-consumed buffer (each thread overwrites its own
            // region only), then one TMA bulk store.
            float4* p4o = &sP[p][0];
            #pragma unroll
            for (int i = 0; i < 9; i++)
                p4o[t * 9 + i] = make_float4(Pu[4 * i], Pu[4 * i + 1], Pu[4 * i + 2], Pu[4 * i + 3]);
            fence_async_shared();
            __syncthreads();           // all STS visible to async proxy
            if (t == 0) {
                tma_store_1d(out_P + base * 36, (p ? sb1 : sb0), P_BYTES);
                tma_store_commit();
                if (k + 2 < nt) {
                    // buffer p gets re-loaded next: its store's smem reads must finish
                    tma_store_wait_read0();
                    issue_load(k + 2);
                }
            }
        } else if (active) {
            float4* op4 = reinterpret_cast<float4*>(out_P + (size_t)b * 36);
            #pragma unroll
            for (int i = 0; i < 9; i++)
                op4[i] = make_float4(Pu[4 * i], Pu[4 * i + 1], Pu[4 * i + 2], Pu[4 * i + 3]);
        }
    }
}

extern "C" void kernel_launch(void* const* d_in, const int* in_sizes, int n_in,
                              void* d_out, int out_size) {
    const float* z   = (const float*)d_in[0];
    const float* u   = (const float*)d_in[1];
    const float* xp  = (const float*)d_in[2];
    const float* Pp  = (const float*)d_in[3];
    const float* qld = (const float*)d_in[4];
    const float* qod = (const float*)d_in[5];
    const float* rld = (const float*)d_in[6];
    const float* rod = (const float*)d_in[7];

    int B = in_sizes[0] / 3;
    float* out_x = (float*)d_out;
    float* out_P = out_x + (size_t)B * 6;

    int ntot = (B + TPB - 1) / TPB;
    int grid = 912;                 // 6 CTAs/SM x 152 SMs, all resident in wave 1
    if (grid > ntot) grid = ntot;

    ekf_kernel<<<grid, TPB>>>(z, u, xp, Pp, qld, qod, rld, rod, out_x, out_P, B);
}

// round 11
// speedup vs baseline: 1.0312x; 1.0193x over previous
#include <cuda_runtime.h>
#include <cstdint>

#define DT_C 0.02f
#define GRAV_C 10.0f
#define THRUST_C 6.0f
#define TORQUE_C 1.0f
#define TPB 128

__device__ __forceinline__ void cp_async16(uint32_t smem_dst, const void* gmem_src) {
    asm volatile("cp.async.cg.shared.global [%0], [%1], 16;"
                 :: "r"(smem_dst), "l"(gmem_src) : "memory");
}
__device__ __forceinline__ void cp_commit() {
    asm volatile("cp.async.commit_group;" ::: "memory");
}

__global__ __launch_bounds__(TPB, 6)
void ekf_kernel(const float* __restrict__ z, const float* __restrict__ u,
                const float* __restrict__ xprev, const float* __restrict__ Pprev,
                const float* __restrict__ qld, const float* __restrict__ qod,
                const float* __restrict__ rld, const float* __restrict__ rod,
                float* __restrict__ out_x, float* __restrict__ out_P, int B) {
    __shared__ float4 sP[2][TPB * 9];   // 36864 B
    __shared__ float sQ[36];
    __shared__ float sR[9];

    const int t = threadIdx.x;
    const int G = gridDim.x;
    const int bid = blockIdx.x;
    const int ntot = (B + TPB - 1) / TPB;
    const int nt = (ntot > bid) ? ((ntot - bid + G - 1) / G) : 0;

    // ---- Build Q = L L^T + 1e-6 I (threads 0..35) and R (36..44), once per CTA ----
    if (t < 36) {
        int i = t / 6, j = t % 6;
        float acc = (i == j) ? 1e-6f : 0.0f;
        #pragma unroll
        for (int k = 0; k < 6; k++) {
            float Lik = (k < i) ? qod[i * (i - 1) / 2 + k] : ((k == i) ? expf(qld[i]) : 0.0f);
            float Ljk = (k < j) ? qod[j * (j - 1) / 2 + k] : ((k == j) ? expf(qld[j]) : 0.0f);
            acc += Lik * Ljk;
        }
        sQ[t] = acc;
    } else if (t < 45) {
        int t2 = t - 36;
        int i = t2 / 3, j = t2 % 3;
        float acc = (i == j) ? 1e-6f : 0.0f;
        #pragma unroll
        for (int k = 0; k < 3; k++) {
            float Lik = (k < i) ? rod[i * (i - 1) / 2 + k] : ((k == i) ? expf(rld[i]) : 0.0f);
            float Ljk = (k < j) ? rod[j * (j - 1) / 2 + k] : ((k == j) ? expf(rld[j]) : 0.0f);
            acc += Lik * Ljk;
        }
        sR[t2] = acc;
    }

    if (nt == 0) return;

    auto issue_tile = [&](int k, int p) {
        int tile = bid + k * G;
        size_t base = (size_t)tile * TPB;
        if (base + TPB <= (size_t)B) {   // full tile: coalesced P staging
            const float4* Pg = reinterpret_cast<const float4*>(Pprev) + base * 9;
            uint32_t sb = (uint32_t)__cvta_generic_to_shared(&sP[p][0]);
            #pragma unroll
            for (int kk = 0; kk < 9; kk++)
                cp_async16(sb + (uint32_t)(t + kk * TPB) * 16u, Pg + t + kk * TPB);
        }
    };

    // ---- Prologue: prefetch first two tiles ----
    issue_tile(0, 0);
    cp_commit();
    if (nt > 1) issue_tile(1, 1);
    cp_commit();   // possibly empty; positional wait keeps group numbering consistent

    for (int k = 0; k < nt; k++) {
        int p = k & 1;
        int tile = bid + k * G;
        size_t base = (size_t)tile * TPB;
        bool full = (base + TPB <= (size_t)B);
        int b = (int)base + t;
        bool active = (b < B);

        // ---- Direct small loads (issued before the pipeline wait; overlap) ----
        float px = 0, py = 0, vx = 0, vy = 0, th = 0, om = 0;
        float u0 = 0, u1 = 0, z0 = 0, z1 = 0, z2 = 0;
        if (active) {
            const float2* x2 = reinterpret_cast<const float2*>(xprev + (size_t)b * 6);
            float2 a = x2[0], bb = x2[1], cc = x2[2];
            px = a.x; py = a.y; vx = bb.x; vy = bb.y; th = cc.x; om = cc.y;
            float2 uu = reinterpret_cast<const float2*>(u)[b];
            u0 = uu.x; u1 = uu.y;
            z0 = z[(size_t)b * 3 + 0];
            z1 = z[(size_t)b * 3 + 1];
            z2 = z[(size_t)b * 3 + 2];
        }

        // ---- Dynamics + Jacobian coefficients (independent of P; hides wait) ----
        float mp = fminf(fmaxf(u0, 0.0f), 1.0f);
        float s, c;
        __sincosf(th, &s, &c);
        float Tm = THRUST_C * mp;
        float nvx = vx + (-Tm * s) * DT_C;
        float nvy = vy + (Tm * c - GRAV_C) * DT_C;
        float nom = om + (TORQUE_C * u1) * DT_C;
        float npx = px + nvx * DT_C;
        float npy = py + nvy * DT_C;
        float nth = th + nom * DT_C;

        float a2 = -Tm * c * DT_C;   // F[2][4]
        float a3 = -Tm * s * DT_C;   // F[3][4]
        float a0 = a2 * DT_C;        // F[0][4]
        float a1 = a3 * DT_C;        // F[1][4]

        if (k + 1 < nt) asm volatile("cp.async.wait_group 1;" ::: "memory");
        else            asm volatile("cp.async.wait_group 0;" ::: "memory");
        __syncthreads();

        // ---- Fetch my P_prev ----
        float Pf[36];
        if (full) {
            #pragma unroll
            for (int i = 0; i < 9; i++) {
                float4 v = sP[p][t * 9 + i];
                Pf[4 * i + 0] = v.x; Pf[4 * i + 1] = v.y;
                Pf[4 * i + 2] = v.z; Pf[4 * i + 3] = v.w;
            }
        } else if (active) {
            const float4* p4 = reinterpret_cast<const float4*>(Pprev + (size_t)b * 36);
            #pragma unroll
            for (int i = 0; i < 9; i++) {
                float4 v = p4[i];
                Pf[4 * i + 0] = v.x; Pf[4 * i + 1] = v.y;
                Pf[4 * i + 2] = v.z; Pf[4 * i + 3] = v.w;
            }
        } else {
            #pragma unroll
            for (int i = 0; i < 36; i++) Pf[i] = 0.0f;
        }
#define Pm(i, j) Pf[(i) * 6 + (j)]

        // ---- P_pred = F P F^T + Q (sparse F: row ops then col ops, in place) ----
        #pragma unroll
        for (int j = 0; j < 6; j++) {
            Pm(0, j) += DT_C * Pm(2, j) + a0 * Pm(4, j);
            Pm(1, j) += DT_C * Pm(3, j) + a1 * Pm(4, j);
            Pm(2, j) += a2 * Pm(4, j);
            Pm(3, j) += a3 * Pm(4, j);
            Pm(4, j) += DT_C * Pm(5, j);
        }
        #pragma unroll
        for (int i = 0; i < 6; i++) {
            Pm(i, 0) += DT_C * Pm(i, 2) + a0 * Pm(i, 4);
            Pm(i, 1) += DT_C * Pm(i, 3) + a1 * Pm(i, 4);
            Pm(i, 2) += a2 * Pm(i, 4);
            Pm(i, 3) += a3 * Pm(i, 4);
            Pm(i, 4) += DT_C * Pm(i, 5);
        }

        // ---- Upper triangle of P_pred + Q ----
        float up[21];
        {
            int kk = 0;
            #pragma unroll
            for (int i = 0; i < 6; i++)
                #pragma unroll
                for (int j = i; j < 6; j++) {
                    up[kk] = Pm(i, j) + sQ[i * 6 + j];
                    kk++;
                }
        }
#undef Pm
#define UIDX(i, j) ((i) * 6 - (i) * ((i) + 1) / 2 + (j))
#define US(i, j) ((i) <= (j) ? up[UIDX(i, j)] : up[UIDX(j, i)])

        // ---- S = P_pred[(0,1,4),(0,1,4)] + R ; symmetric 3x3 inverse ----
        float S00 = US(0, 0) + sR[0];
        float S01 = US(0, 1) + sR[1];
        float S02 = US(0, 4) + sR[2];
        float S11 = US(1, 1) + sR[4];
        float S12 = US(1, 4) + sR[5];
        float S22 = US(4, 4) + sR[8];

        float i00 = S11 * S22 - S12 * S12;
        float i01 = S02 * S12 - S01 * S22;
        float i02 = S01 * S12 - S02 * S11;
        float i11 = S00 * S22 - S02 * S02;
        float i12 = S01 * S02 - S00 * S12;
        float i22 = S00 * S11 - S01 * S01;
        float invdet = 1.0f / (S00 * i00 + S01 * i01 + S02 * i02);
        i00 *= invdet; i01 *= invdet; i02 *= invdet;
        i11 *= invdet; i12 *= invdet; i22 *= invdet;

        // ---- K[k] = Si * (P[0][k], P[1][k], P[4][k]) ----
        float K[6][3];
        #pragma unroll
        for (int kk = 0; kk < 6; kk++) {
            float h0 = US(0, kk), h1 = US(1, kk), h2 = US(4, kk);
            K[kk][0] = h0 * i00 + h1 * i01 + h2 * i02;
            K[kk][1] = h0 * i01 + h1 * i11 + h2 * i12;
            K[kk][2] = h0 * i02 + h1 * i12 + h2 * i22;
        }

        // ---- x_upd (direct store, float2) ----
        float y0 = z0 - npx, y1 = z1 - npy, y2 = z2 - nth;
        if (active) {
            float xpred[6] = {npx, npy, nvx, nvy, nth, nom};
            float2* ox2 = reinterpret_cast<float2*>(out_x + (size_t)b * 6);
            #pragma unroll
            for (int i = 0; i < 3; i++) {
                float v0 = xpred[2 * i]     + K[2 * i][0] * y0 + K[2 * i][1] * y1 + K[2 * i][2] * y2;
                float v1 = xpred[2 * i + 1] + K[2 * i + 1][0] * y0 + K[2 * i + 1][1] * y1 + K[2 * i + 1][2] * y2;
                ox2[i] = make_float2(v0, v1);
            }
        }

        // ---- P_upd = P_pred - K (H P_pred), symmetric ----
        float Pu[36];
        #pragma unroll
        for (int i = 0; i < 6; i++)
            #pragma unroll
            for (int j = i; j < 6; j++) {
                float v = US(i, j)
                    - K[i][0] * US(0, j) - K[i][1] * US(1, j) - K[i][2] * US(4, j);
                Pu[i * 6 + j] = v;
                Pu[j * 6 + i] = v;
            }
#undef US
#undef UIDX

        // ---- P store ----
        if (full) {
            // stage into the just-consumed buffer (per-thread region), then coalesced STG
            #pragma unroll
            for (int i = 0; i < 9; i++)
                sP[p][t * 9 + i] = make_float4(Pu[4 * i], Pu[4 * i + 1], Pu[4 * i + 2], Pu[4 * i + 3]);
            __syncthreads();
            float4* Po = reinterpret_cast<float4*>(out_P) + base * 9;
            #pragma unroll
            for (int kk = 0; kk < 9; kk++)
                Po[t + kk * TPB] = sP[p][t + kk * TPB];
            __syncthreads();   // LDS-for-STG done before buffer p is re-prefetched
        } else if (active) {
            float4* op4 = reinterpret_cast<float4*>(out_P + (size_t)b * 36);
            #pragma unroll
            for (int i = 0; i < 9; i++)
                op4[i] = make_float4(Pu[4 * i], Pu[4 * i + 1], Pu[4 * i + 2], Pu[4 * i + 3]);
        }

        // ---- Prefetch tile k+2 into buffer p ----
        if (k + 2 < nt) issue_tile(k + 2, p);
        cp_commit();
    }
}

extern "C" void kernel_launch(void* const* d_in, const int* in_sizes, int n_in,
                              void* d_out, int out_size) {
    const float* z   = (const float*)d_in[0];
    const float* u   = (const float*)d_in[1];
    const float* xp  = (const float*)d_in[2];
    const float* Pp  = (const float*)d_in[3];
    const float* qld = (const float*)d_in[4];
    const float* qod = (const float*)d_in[5];
    const float* rld = (const float*)d_in[6];
    const float* rod = (const float*)d_in[7];

    int B = in_sizes[0] / 3;
    float* out_x = (float*)d_out;
    float* out_P = out_x + (size_t)B * 6;

    int ntot = (B + TPB - 1) / TPB;
    int grid = 912;                 // 6 CTAs/SM x 152 SMs, all resident in wave 1
    if (grid > ntot) grid = ntot;

    ekf_kernel<<<grid, TPB>>>(z, u, xp, Pp, qld, qod, rld, rod, out_x, out_P, B);
}